// round 1
// baseline (speedup 1.0000x reference)
#include <cuda_runtime.h>

// ---------------------------------------------------------------------------
// LSTM (SEQ=512, BATCH=512, INPUT=128, HIDDEN=256) + final Linear(256->1).
//
// Strategy (round 0 baseline, see theory): batch-split persistent kernel.
// Each CTA owns BTILE=4 batch rows and runs the full 512-step recurrence with
// NO cross-CTA synchronization (the LSTM recurrence is batch-independent).
// Weights are pre-transposed to k-major (g_Wt[k][n]) so the gate-column loads
// are coalesced LDG.128 per warp; W stays L2-resident (1.5 MB).
// ---------------------------------------------------------------------------

#define SEQ     512
#define BATCH   512
#define INPUT   128
#define HIDDEN  256
#define GATES   (4 * HIDDEN)        // 1024
#define KTOT    (INPUT + HIDDEN)    // 384
#define BTILE   4
#define NCTA    (BATCH / BTILE)     // 128
#define NTHR    256

// Scratch (no cudaMalloc allowed): transposed/concatenated weights + fused bias.
__device__ float g_Wt[KTOT * GATES];   // g_Wt[k][n] = (k<128 ? W_ih[n][k] : W_hh[n][k-128])
__device__ float g_b[GATES];           // b_ih + b_hh

// ---------------------------------------------------------------------------
__global__ void prep_kernel(const float* __restrict__ W_ih,
                            const float* __restrict__ W_hh,
                            const float* __restrict__ b_ih,
                            const float* __restrict__ b_hh) {
    int idx = blockIdx.x * blockDim.x + threadIdx.x;
    if (idx < KTOT * GATES) {
        int k = idx / GATES;
        int n = idx - k * GATES;
        g_Wt[idx] = (k < INPUT) ? W_ih[n * INPUT + k]
                                : W_hh[n * HIDDEN + (k - INPUT)];
    }
    if (idx < GATES) {
        g_b[idx] = b_ih[idx] + b_hh[idx];
    }
}

// ---------------------------------------------------------------------------
__device__ __forceinline__ float sigf(float v) {
    return 1.0f / (1.0f + __expf(-v));
}
__device__ __forceinline__ float tanh_fast(float v) {
    // tanh(x) = 2*sigmoid(2x) - 1 ; __expf rel err ~2^-22, well under tolerance.
    return 2.0f / (1.0f + __expf(-2.0f * v)) - 1.0f;
}

__global__ void __launch_bounds__(NTHR, 1)
lstm_kernel(const float* __restrict__ x,
            const float* __restrict__ W_out,
            const float* __restrict__ b_out,
            float* __restrict__ out) {
    __shared__ float xh[BTILE][KTOT];    // [4][384]: [0:128)=x_t, [128:384)=h
    __shared__ float gsm[BTILE][GATES];  // gate pre-activations for regrouping

    const int tid = threadIdx.x;
    const int bb  = blockIdx.x * BTILE;  // first batch row of this CTA

    // Zero the whole xh (h part must start at 0; x part is overwritten anyway).
    for (int i = tid; i < BTILE * KTOT; i += NTHR)
        (&xh[0][0])[i] = 0.0f;

    // Per-thread constants: this thread owns gate columns [4*tid, 4*tid+4).
    const float4 bias = *reinterpret_cast<const float4*>(g_b + 4 * tid);
    const float4* Wt4 = reinterpret_cast<const float4*>(g_Wt) + tid; // row stride GATES/4

    // Cell state: this thread owns hidden units u = 4*tid .. 4*tid+3,
    // i.e. row ur = tid>>6, n = (tid&63)*4 .. +3 (all 4 in the same row).
    const int ur = tid >> 6;
    const int nb = (tid & 63) * 4;
    float c0 = 0.0f, c1 = 0.0f, c2 = 0.0f, c3 = 0.0f;

    for (int t = 0; t < SEQ; ++t) {
        // ---- load x_t tile: 4 rows x 128 = 512 floats, fully coalesced ----
        if (tid < 128) {
            const float4* xsrc = reinterpret_cast<const float4*>(
                x + ((size_t)t * BATCH + bb) * INPUT);
            float4 v = xsrc[tid];
            int r  = tid >> 5;           // (tid*4)/128
            int ci = (tid & 31) * 4;
            *reinterpret_cast<float4*>(&xh[r][ci]) = v;
        }
        __syncthreads();   // xh fully valid (x_t + h from previous step)

        // ---- gates = bias + xh @ Wt  (per thread: 4 rows x 4 cols) ----
        float4 a0 = bias, a1 = bias, a2 = bias, a3 = bias;
        #pragma unroll 4
        for (int k4 = 0; k4 < KTOT / 4; ++k4) {
            float4 h0 = *reinterpret_cast<const float4*>(&xh[0][k4 * 4]);
            float4 h1 = *reinterpret_cast<const float4*>(&xh[1][k4 * 4]);
            float4 h2 = *reinterpret_cast<const float4*>(&xh[2][k4 * 4]);
            float4 h3 = *reinterpret_cast<const float4*>(&xh[3][k4 * 4]);
            #pragma unroll
            for (int kk = 0; kk < 4; ++kk) {
                float4 w = Wt4[(size_t)(k4 * 4 + kk) * (GATES / 4)];
                float v0 = (&h0.x)[kk];
                float v1 = (&h1.x)[kk];
                float v2 = (&h2.x)[kk];
                float v3 = (&h3.x)[kk];
                a0.x += v0 * w.x; a0.y += v0 * w.y; a0.z += v0 * w.z; a0.w += v0 * w.w;
                a1.x += v1 * w.x; a1.y += v1 * w.y; a1.z += v1 * w.z; a1.w += v1 * w.w;
                a2.x += v2 * w.x; a2.y += v2 * w.y; a2.z += v2 * w.z; a2.w += v2 * w.w;
                a3.x += v3 * w.x; a3.y += v3 * w.y; a3.z += v3 * w.z; a3.w += v3 * w.w;
            }
        }
        *reinterpret_cast<float4*>(&gsm[0][4 * tid]) = a0;
        *reinterpret_cast<float4*>(&gsm[1][4 * tid]) = a1;
        *reinterpret_cast<float4*>(&gsm[2][4 * tid]) = a2;
        *reinterpret_cast<float4*>(&gsm[3][4 * tid]) = a3;
        __syncthreads();   // gates staged

        // ---- cell/hidden update for this thread's 4 units (row ur) ----
        {
            float4 gi = *reinterpret_cast<const float4*>(&gsm[ur][nb]);
            float4 gf = *reinterpret_cast<const float4*>(&gsm[ur][HIDDEN + nb]);
            float4 gg = *reinterpret_cast<const float4*>(&gsm[ur][2 * HIDDEN + nb]);
            float4 go = *reinterpret_cast<const float4*>(&gsm[ur][3 * HIDDEN + nb]);

            c0 = sigf(gf.x) * c0 + sigf(gi.x) * tanh_fast(gg.x);
            c1 = sigf(gf.y) * c1 + sigf(gi.y) * tanh_fast(gg.y);
            c2 = sigf(gf.z) * c2 + sigf(gi.z) * tanh_fast(gg.z);
            c3 = sigf(gf.w) * c3 + sigf(gi.w) * tanh_fast(gg.w);

            float4 hv;
            hv.x = sigf(go.x) * tanh_fast(c0);
            hv.y = sigf(go.y) * tanh_fast(c1);
            hv.z = sigf(go.z) * tanh_fast(c2);
            hv.w = sigf(go.w) * tanh_fast(c3);
            *reinterpret_cast<float4*>(&xh[ur][INPUT + nb]) = hv;
        }
        // No third sync needed: the next iteration's __syncthreads() (after the
        // disjoint x-region load) orders these h writes before any gate read.
    }
    __syncthreads();

    // ---- final projection: out[bb+r] = h_n[r] . W_out + b_out ----
    const int w    = tid >> 5;
    const int lane = tid & 31;
    if (w < BTILE) {
        float s = 0.0f;
        #pragma unroll
        for (int n = lane; n < HIDDEN; n += 32)
            s += xh[w][INPUT + n] * W_out[n];
        #pragma unroll
        for (int off = 16; off > 0; off >>= 1)
            s += __shfl_xor_sync(0xFFFFFFFFu, s, off);
        if (lane == 0)
            out[bb + w] = s + b_out[0];
    }
}

// ---------------------------------------------------------------------------
extern "C" void kernel_launch(void* const* d_in, const int* in_sizes, int n_in,
                              void* d_out, int out_size) {
    const float* x     = (const float*)d_in[0];
    const float* W_ih  = (const float*)d_in[1];
    const float* W_hh  = (const float*)d_in[2];
    const float* b_ih  = (const float*)d_in[3];
    const float* b_hh  = (const float*)d_in[4];
    const float* W_out = (const float*)d_in[5];
    const float* b_out = (const float*)d_in[6];
    float* out = (float*)d_out;

    prep_kernel<<<(KTOT * GATES + 255) / 256, 256>>>(W_ih, W_hh, b_ih, b_hh);
    lstm_kernel<<<NCTA, NTHR>>>(x, W_out, b_out, out);
}

// round 2
// speedup vs baseline: 1.0274x; 1.0274x over previous
#include <cuda_runtime.h>

// ---------------------------------------------------------------------------
// Round 2: weight-stationary hidden-split LSTM + packed f32x2 FMA.
//
// Grid = 8 batch-groups x 16 hidden-slices = 128 CTAs (all co-resident,
// 1 CTA/SM forced by smem). Each CTA keeps its 384x64 W slice in smem for the
// whole sequence (zero per-step L2 weight traffic). Per step, the 16 CTAs of
// a batch group exchange h slices via a double-buffered global buffer and a
// sense-reversing group barrier (512 barriers/launch — even, so the
// persistent sense flag returns to its initial state across graph replays).
// Gate GEMM uses fma.rn.f32x2 (2 MACs/instr) -> fp32 full-rate per SM.
// ---------------------------------------------------------------------------

#define SEQ     512
#define BATCH   512
#define INPUT   128
#define HIDDEN  256
#define KTOT    (INPUT + HIDDEN)   // 384
#define BT      64                 // batch rows per CTA
#define HS      16                 // hidden units per CTA
#define NGROUP  (BATCH / BT)       // 8
#define NSLICE  (HIDDEN / HS)      // 16
#define NCTA    (NGROUP * NSLICE)  // 128
#define NTHR    256
#define LCOLS   (4 * HS)           // 64 local gate columns
#define XH_LD   388                // padded xh row stride (floats)
#define GLD     68                 // padded gate-staging row stride

#define SMEM_FLOATS (KTOT * LCOLS + BT * XH_LD + BT * GLD)
#define SMEM_BYTES  (SMEM_FLOATS * 4)   // 215040 B

// Cross-CTA h exchange (double buffered) + group barrier state.
__device__ float g_h[2][NGROUP][BT][HIDDEN];
__device__ int   g_bar_count[NGROUP];
__device__ int   g_bar_sense[NGROUP];

// ---------------------------------------------------------------------------
__device__ __forceinline__ unsigned long long splat2(float v) {
    unsigned long long r;
    asm("mov.b64 %0, {%1, %1};" : "=l"(r) : "f"(v));
    return r;
}
__device__ __forceinline__ unsigned long long pack2(float a, float b) {
    unsigned long long r;
    asm("mov.b64 %0, {%1, %2};" : "=l"(r) : "f"(a), "f"(b));
    return r;
}
__device__ __forceinline__ float2 unpack2(unsigned long long u) {
    float2 f;
    asm("mov.b64 {%0, %1}, %2;" : "=f"(f.x), "=f"(f.y) : "l"(u));
    return f;
}
__device__ __forceinline__ unsigned long long fma2(unsigned long long a,
                                                   unsigned long long b,
                                                   unsigned long long c) {
    unsigned long long d;
    asm("fma.rn.f32x2 %0, %1, %2, %3;" : "=l"(d) : "l"(a), "l"(b), "l"(c));
    return d;
}

__device__ __forceinline__ float sigf(float v) {
    return 1.0f / (1.0f + __expf(-v));
}
__device__ __forceinline__ float tanh_fast(float v) {
    return 2.0f / (1.0f + __expf(-2.0f * v)) - 1.0f;
}

// ---------------------------------------------------------------------------
__global__ void __launch_bounds__(NTHR, 1)
lstm_kernel(const float* __restrict__ x,
            const float* __restrict__ W_ih,
            const float* __restrict__ W_hh,
            const float* __restrict__ b_ih,
            const float* __restrict__ b_hh,
            const float* __restrict__ W_out,
            const float* __restrict__ b_out,
            float* __restrict__ out) {
    extern __shared__ float sm[];
    float* Wsm = sm;                        // [KTOT][LCOLS]
    float* xh  = Wsm + KTOT * LCOLS;        // [BT][XH_LD]: [0:128)=x, [128:384)=h
    float* gsm = xh + BT * XH_LD;           // [BT][GLD] gate staging

    const int tid   = threadIdx.x;
    const int g     = blockIdx.x >> 4;      // batch group
    const int slice = blockIdx.x & 15;      // hidden slice
    const int bb    = g * BT;

    // ---- one-time: load W slice transposed into smem -----------------------
    // local col c (0..63): gate type gt=c>>4, unit=c&15 -> global gate col.
    for (int i = tid; i < KTOT * LCOLS; i += NTHR) {
        int c = i / KTOT;
        int k = i - c * KTOT;
        int gcol = (c >> 4) * HIDDEN + slice * HS + (c & 15);
        float w = (k < INPUT) ? W_ih[(size_t)gcol * INPUT + k]
                              : W_hh[(size_t)gcol * HIDDEN + (k - INPUT)];
        Wsm[k * LCOLS + c] = w;
    }
    // zero xh (h region must start at 0)
    for (int i = tid; i < BT * XH_LD; i += NTHR) xh[i] = 0.0f;

    // ---- per-thread gate-GEMM tile: rows r0..r0+3, cols c4..c4+3 -----------
    const int r0 = (tid >> 4) * 4;
    const int c4 = (tid & 15) * 4;
    const int gcol0 = (c4 >> 4) * HIDDEN + slice * HS + (c4 & 15);
    const unsigned long long Blo = pack2(b_ih[gcol0 + 0] + b_hh[gcol0 + 0],
                                         b_ih[gcol0 + 1] + b_hh[gcol0 + 1]);
    const unsigned long long Bhi = pack2(b_ih[gcol0 + 2] + b_hh[gcol0 + 2],
                                         b_ih[gcol0 + 3] + b_hh[gcol0 + 3]);
    const float* xr0 = &xh[(r0 + 0) * XH_LD];
    const float* xr1 = &xh[(r0 + 1) * XH_LD];
    const float* xr2 = &xh[(r0 + 2) * XH_LD];
    const float* xr3 = &xh[(r0 + 3) * XH_LD];

    // ---- per-thread cell state: row rr, hidden units u0..u0+3 --------------
    const int rr = tid >> 2;
    const int u0 = (tid & 3) * 4;
    float c0 = 0.0f, c1 = 0.0f, c2 = 0.0f, c3 = 0.0f;

    int sense = 1;
    __syncthreads();   // Wsm + xh ready

    for (int s = 0; s < SEQ; ++s) {
        // ---- stage x_t rows (coalesced) ----
        const float4* xs = reinterpret_cast<const float4*>(
            x + ((size_t)s * BATCH + bb) * INPUT);
        for (int i = tid; i < BT * INPUT / 4; i += NTHR) {
            float4 v = xs[i];
            int r = i >> 5, cc = (i & 31) * 4;
            *reinterpret_cast<float4*>(&xh[r * XH_LD + cc]) = v;
        }
        // ---- stage full h(s-1) from the exchange buffer ----
        if (s > 0) {
            const float4* hs = reinterpret_cast<const float4*>(
                &g_h[(s - 1) & 1][g][0][0]);
            for (int i = tid; i < BT * HIDDEN / 4; i += NTHR) {
                float4 v = hs[i];
                int r = i >> 6, cc = (i & 63) * 4;
                *reinterpret_cast<float4*>(&xh[r * XH_LD + INPUT + cc]) = v;
            }
        }
        __syncthreads();

        // ---- gates = bias + xh @ Wslice (4 rows x 4 cols, packed f32x2) ----
        unsigned long long A00 = Blo, A01 = Bhi, A10 = Blo, A11 = Bhi;
        unsigned long long A20 = Blo, A21 = Bhi, A30 = Blo, A31 = Bhi;
        #pragma unroll 4
        for (int k4 = 0; k4 < KTOT / 4; ++k4) {
            const int kb = 4 * k4;
            ulonglong2 wa = *reinterpret_cast<const ulonglong2*>(&Wsm[(kb + 0) * LCOLS + c4]);
            ulonglong2 wb = *reinterpret_cast<const ulonglong2*>(&Wsm[(kb + 1) * LCOLS + c4]);
            ulonglong2 wc = *reinterpret_cast<const ulonglong2*>(&Wsm[(kb + 2) * LCOLS + c4]);
            ulonglong2 wd = *reinterpret_cast<const ulonglong2*>(&Wsm[(kb + 3) * LCOLS + c4]);
            float4 h0 = *reinterpret_cast<const float4*>(xr0 + kb);
            float4 h1 = *reinterpret_cast<const float4*>(xr1 + kb);
            float4 h2 = *reinterpret_cast<const float4*>(xr2 + kb);
            float4 h3 = *reinterpret_cast<const float4*>(xr3 + kb);
            unsigned long long v;
            v = splat2(h0.x); A00 = fma2(v, wa.x, A00); A01 = fma2(v, wa.y, A01);
            v = splat2(h1.x); A10 = fma2(v, wa.x, A10); A11 = fma2(v, wa.y, A11);
            v = splat2(h2.x); A20 = fma2(v, wa.x, A20); A21 = fma2(v, wa.y, A21);
            v = splat2(h3.x); A30 = fma2(v, wa.x, A30); A31 = fma2(v, wa.y, A31);
            v = splat2(h0.y); A00 = fma2(v, wb.x, A00); A01 = fma2(v, wb.y, A01);
            v = splat2(h1.y); A10 = fma2(v, wb.x, A10); A11 = fma2(v, wb.y, A11);
            v = splat2(h2.y); A20 = fma2(v, wb.x, A20); A21 = fma2(v, wb.y, A21);
            v = splat2(h3.y); A30 = fma2(v, wb.x, A30); A31 = fma2(v, wb.y, A31);
            v = splat2(h0.z); A00 = fma2(v, wc.x, A00); A01 = fma2(v, wc.y, A01);
            v = splat2(h1.z); A10 = fma2(v, wc.x, A10); A11 = fma2(v, wc.y, A11);
            v = splat2(h2.z); A20 = fma2(v, wc.x, A20); A21 = fma2(v, wc.y, A21);
            v = splat2(h3.z); A30 = fma2(v, wc.x, A30); A31 = fma2(v, wc.y, A31);
            v = splat2(h0.w); A00 = fma2(v, wd.x, A00); A01 = fma2(v, wd.y, A01);
            v = splat2(h1.w); A10 = fma2(v, wd.x, A10); A11 = fma2(v, wd.y, A11);
            v = splat2(h2.w); A20 = fma2(v, wd.x, A20); A21 = fma2(v, wd.y, A21);
            v = splat2(h3.w); A30 = fma2(v, wd.x, A30); A31 = fma2(v, wd.y, A31);
        }
        {
            float2 p, q;
            p = unpack2(A00); q = unpack2(A01);
            *reinterpret_cast<float4*>(&gsm[(r0 + 0) * GLD + c4]) = make_float4(p.x, p.y, q.x, q.y);
            p = unpack2(A10); q = unpack2(A11);
            *reinterpret_cast<float4*>(&gsm[(r0 + 1) * GLD + c4]) = make_float4(p.x, p.y, q.x, q.y);
            p = unpack2(A20); q = unpack2(A21);
            *reinterpret_cast<float4*>(&gsm[(r0 + 2) * GLD + c4]) = make_float4(p.x, p.y, q.x, q.y);
            p = unpack2(A30); q = unpack2(A31);
            *reinterpret_cast<float4*>(&gsm[(r0 + 3) * GLD + c4]) = make_float4(p.x, p.y, q.x, q.y);
        }
        __syncthreads();

        // ---- cell/hidden update for (row rr, units u0..u0+3) ----
        {
            float4 gi = *reinterpret_cast<const float4*>(&gsm[rr * GLD +  0 + u0]);
            float4 gf = *reinterpret_cast<const float4*>(&gsm[rr * GLD + 16 + u0]);
            float4 gg = *reinterpret_cast<const float4*>(&gsm[rr * GLD + 32 + u0]);
            float4 go = *reinterpret_cast<const float4*>(&gsm[rr * GLD + 48 + u0]);

            c0 = sigf(gf.x) * c0 + sigf(gi.x) * tanh_fast(gg.x);
            c1 = sigf(gf.y) * c1 + sigf(gi.y) * tanh_fast(gg.y);
            c2 = sigf(gf.z) * c2 + sigf(gi.z) * tanh_fast(gg.z);
            c3 = sigf(gf.w) * c3 + sigf(gi.w) * tanh_fast(gg.w);

            float4 hv;
            hv.x = sigf(go.x) * tanh_fast(c0);
            hv.y = sigf(go.y) * tanh_fast(c1);
            hv.z = sigf(go.z) * tanh_fast(c2);
            hv.w = sigf(go.w) * tanh_fast(c3);
            *reinterpret_cast<float4*>(&g_h[s & 1][g][rr][slice * HS + u0]) = hv;
        }
        __syncthreads();   // all h writes issued; gsm/xh reads for step s done

        // ---- sense-reversing group barrier (16 CTAs of this batch group) ----
        if (tid == 0) {
            __threadfence();                         // release h writes
            int prev = atomicAdd(&g_bar_count[g], 1);
            if (prev == NSLICE - 1) {
                atomicExch(&g_bar_count[g], 0);
                __threadfence();                     // reset visible before sense
                atomicExch(&g_bar_sense[g], sense);
            } else {
                volatile int* sp = &g_bar_sense[g];
                while (*sp != sense) __nanosleep(32);
                __threadfence();                     // acquire peers' h writes
            }
        }
        __syncthreads();
        sense ^= 1;
    }

    // ---- final projection (slice 0 of each group): out = h_n @ W_out + b ---
    if (slice == 0) {
        const int wid = tid >> 5, lane = tid & 31;
        const float bo = b_out[0];
        for (int r = wid; r < BT; r += 8) {
            const float* hr = &g_h[(SEQ - 1) & 1][g][r][0];
            float ssum = 0.0f;
            #pragma unroll
            for (int n = lane; n < HIDDEN; n += 32)
                ssum += hr[n] * W_out[n];
            #pragma unroll
            for (int off = 16; off > 0; off >>= 1)
                ssum += __shfl_xor_sync(0xFFFFFFFFu, ssum, off);
            if (lane == 0) out[bb + r] = ssum + bo;
        }
    }
}

// ---------------------------------------------------------------------------
extern "C" void kernel_launch(void* const* d_in, const int* in_sizes, int n_in,
                              void* d_out, int out_size) {
    const float* x     = (const float*)d_in[0];
    const float* W_ih  = (const float*)d_in[1];
    const float* W_hh  = (const float*)d_in[2];
    const float* b_ih  = (const float*)d_in[3];
    const float* b_hh  = (const float*)d_in[4];
    const float* W_out = (const float*)d_in[5];
    const float* b_out = (const float*)d_in[6];
    float* out = (float*)d_out;

    cudaFuncSetAttribute(lstm_kernel,
                         cudaFuncAttributeMaxDynamicSharedMemorySize, SMEM_BYTES);
    lstm_kernel<<<NCTA, NTHR, SMEM_BYTES>>>(x, W_ih, W_hh, b_ih, b_hh,
                                            W_out, b_out, out);
}

// round 3
// speedup vs baseline: 1.0277x; 1.0004x over previous
#include <cuda_runtime.h>

// ---------------------------------------------------------------------------
// Round 2: weight-stationary hidden-split LSTM + packed f32x2 FMA.
//
// Grid = 8 batch-groups x 16 hidden-slices = 128 CTAs (all co-resident,
// 1 CTA/SM forced by smem). Each CTA keeps its 384x64 W slice in smem for the
// whole sequence (zero per-step L2 weight traffic). Per step, the 16 CTAs of
// a batch group exchange h slices via a double-buffered global buffer and a
// sense-reversing group barrier (512 barriers/launch — even, so the
// persistent sense flag returns to its initial state across graph replays).
// Gate GEMM uses fma.rn.f32x2 (2 MACs/instr) -> fp32 full-rate per SM.
// ---------------------------------------------------------------------------

#define SEQ     512
#define BATCH   512
#define INPUT   128
#define HIDDEN  256
#define KTOT    (INPUT + HIDDEN)   // 384
#define BT      64                 // batch rows per CTA
#define HS      16                 // hidden units per CTA
#define NGROUP  (BATCH / BT)       // 8
#define NSLICE  (HIDDEN / HS)      // 16
#define NCTA    (NGROUP * NSLICE)  // 128
#define NTHR    256
#define LCOLS   (4 * HS)           // 64 local gate columns
#define XH_LD   388                // padded xh row stride (floats)
#define GLD     68                 // padded gate-staging row stride

#define SMEM_FLOATS (KTOT * LCOLS + BT * XH_LD + BT * GLD)
#define SMEM_BYTES  (SMEM_FLOATS * 4)   // 215040 B

// Cross-CTA h exchange (double buffered) + group barrier state.
__device__ float g_h[2][NGROUP][BT][HIDDEN];
__device__ int   g_bar_count[NGROUP];
__device__ int   g_bar_sense[NGROUP];

// ---------------------------------------------------------------------------
__device__ __forceinline__ unsigned long long splat2(float v) {
    unsigned long long r;
    asm("mov.b64 %0, {%1, %1};" : "=l"(r) : "f"(v));
    return r;
}
__device__ __forceinline__ unsigned long long pack2(float a, float b) {
    unsigned long long r;
    asm("mov.b64 %0, {%1, %2};" : "=l"(r) : "f"(a), "f"(b));
    return r;
}
__device__ __forceinline__ float2 unpack2(unsigned long long u) {
    float2 f;
    asm("mov.b64 {%0, %1}, %2;" : "=f"(f.x), "=f"(f.y) : "l"(u));
    return f;
}
__device__ __forceinline__ unsigned long long fma2(unsigned long long a,
                                                   unsigned long long b,
                                                   unsigned long long c) {
    unsigned long long d;
    asm("fma.rn.f32x2 %0, %1, %2, %3;" : "=l"(d) : "l"(a), "l"(b), "l"(c));
    return d;
}

__device__ __forceinline__ float sigf(float v) {
    return 1.0f / (1.0f + __expf(-v));
}
__device__ __forceinline__ float tanh_fast(float v) {
    return 2.0f / (1.0f + __expf(-2.0f * v)) - 1.0f;
}

// ---------------------------------------------------------------------------
__global__ void __launch_bounds__(NTHR, 1)
lstm_kernel(const float* __restrict__ x,
            const float* __restrict__ W_ih,
            const float* __restrict__ W_hh,
            const float* __restrict__ b_ih,
            const float* __restrict__ b_hh,
            const float* __restrict__ W_out,
            const float* __restrict__ b_out,
            float* __restrict__ out) {
    extern __shared__ float sm[];
    float* Wsm = sm;                        // [KTOT][LCOLS]
    float* xh  = Wsm + KTOT * LCOLS;        // [BT][XH_LD]: [0:128)=x, [128:384)=h
    float* gsm = xh + BT * XH_LD;           // [BT][GLD] gate staging

    const int tid   = threadIdx.x;
    const int g     = blockIdx.x >> 4;      // batch group
    const int slice = blockIdx.x & 15;      // hidden slice
    const int bb    = g * BT;

    // ---- one-time: load W slice transposed into smem -----------------------
    // local col c (0..63): gate type gt=c>>4, unit=c&15 -> global gate col.
    for (int i = tid; i < KTOT * LCOLS; i += NTHR) {
        int c = i / KTOT;
        int k = i - c * KTOT;
        int gcol = (c >> 4) * HIDDEN + slice * HS + (c & 15);
        float w = (k < INPUT) ? W_ih[(size_t)gcol * INPUT + k]
                              : W_hh[(size_t)gcol * HIDDEN + (k - INPUT)];
        Wsm[k * LCOLS + c] = w;
    }
    // zero xh (h region must start at 0)
    for (int i = tid; i < BT * XH_LD; i += NTHR) xh[i] = 0.0f;

    // ---- per-thread gate-GEMM tile: rows r0..r0+3, cols c4..c4+3 -----------
    const int r0 = (tid >> 4) * 4;
    const int c4 = (tid & 15) * 4;
    const int gcol0 = (c4 >> 4) * HIDDEN + slice * HS + (c4 & 15);
    const unsigned long long Blo = pack2(b_ih[gcol0 + 0] + b_hh[gcol0 + 0],
                                         b_ih[gcol0 + 1] + b_hh[gcol0 + 1]);
    const unsigned long long Bhi = pack2(b_ih[gcol0 + 2] + b_hh[gcol0 + 2],
                                         b_ih[gcol0 + 3] + b_hh[gcol0 + 3]);
    const float* xr0 = &xh[(r0 + 0) * XH_LD];
    const float* xr1 = &xh[(r0 + 1) * XH_LD];
    const float* xr2 = &xh[(r0 + 2) * XH_LD];
    const float* xr3 = &xh[(r0 + 3) * XH_LD];

    // ---- per-thread cell state: row rr, hidden units u0..u0+3 --------------
    const int rr = tid >> 2;
    const int u0 = (tid & 3) * 4;
    float c0 = 0.0f, c1 = 0.0f, c2 = 0.0f, c3 = 0.0f;

    int sense = 1;
    __syncthreads();   // Wsm + xh ready

    for (int s = 0; s < SEQ; ++s) {
        // ---- stage x_t rows (coalesced) ----
        const float4* xs = reinterpret_cast<const float4*>(
            x + ((size_t)s * BATCH + bb) * INPUT);
        for (int i = tid; i < BT * INPUT / 4; i += NTHR) {
            float4 v = xs[i];
            int r = i >> 5, cc = (i & 31) * 4;
            *reinterpret_cast<float4*>(&xh[r * XH_LD + cc]) = v;
        }
        // ---- stage full h(s-1) from the exchange buffer ----
        if (s > 0) {
            const float4* hs = reinterpret_cast<const float4*>(
                &g_h[(s - 1) & 1][g][0][0]);
            for (int i = tid; i < BT * HIDDEN / 4; i += NTHR) {
                float4 v = hs[i];
                int r = i >> 6, cc = (i & 63) * 4;
                *reinterpret_cast<float4*>(&xh[r * XH_LD + INPUT + cc]) = v;
            }
        }
        __syncthreads();

        // ---- gates = bias + xh @ Wslice (4 rows x 4 cols, packed f32x2) ----
        unsigned long long A00 = Blo, A01 = Bhi, A10 = Blo, A11 = Bhi;
        unsigned long long A20 = Blo, A21 = Bhi, A30 = Blo, A31 = Bhi;
        #pragma unroll 4
        for (int k4 = 0; k4 < KTOT / 4; ++k4) {
            const int kb = 4 * k4;
            ulonglong2 wa = *reinterpret_cast<const ulonglong2*>(&Wsm[(kb + 0) * LCOLS + c4]);
            ulonglong2 wb = *reinterpret_cast<const ulonglong2*>(&Wsm[(kb + 1) * LCOLS + c4]);
            ulonglong2 wc = *reinterpret_cast<const ulonglong2*>(&Wsm[(kb + 2) * LCOLS + c4]);
            ulonglong2 wd = *reinterpret_cast<const ulonglong2*>(&Wsm[(kb + 3) * LCOLS + c4]);
            float4 h0 = *reinterpret_cast<const float4*>(xr0 + kb);
            float4 h1 = *reinterpret_cast<const float4*>(xr1 + kb);
            float4 h2 = *reinterpret_cast<const float4*>(xr2 + kb);
            float4 h3 = *reinterpret_cast<const float4*>(xr3 + kb);
            unsigned long long v;
            v = splat2(h0.x); A00 = fma2(v, wa.x, A00); A01 = fma2(v, wa.y, A01);
            v = splat2(h1.x); A10 = fma2(v, wa.x, A10); A11 = fma2(v, wa.y, A11);
            v = splat2(h2.x); A20 = fma2(v, wa.x, A20); A21 = fma2(v, wa.y, A21);
            v = splat2(h3.x); A30 = fma2(v, wa.x, A30); A31 = fma2(v, wa.y, A31);
            v = splat2(h0.y); A00 = fma2(v, wb.x, A00); A01 = fma2(v, wb.y, A01);
            v = splat2(h1.y); A10 = fma2(v, wb.x, A10); A11 = fma2(v, wb.y, A11);
            v = splat2(h2.y); A20 = fma2(v, wb.x, A20); A21 = fma2(v, wb.y, A21);
            v = splat2(h3.y); A30 = fma2(v, wb.x, A30); A31 = fma2(v, wb.y, A31);
            v = splat2(h0.z); A00 = fma2(v, wc.x, A00); A01 = fma2(v, wc.y, A01);
            v = splat2(h1.z); A10 = fma2(v, wc.x, A10); A11 = fma2(v, wc.y, A11);
            v = splat2(h2.z); A20 = fma2(v, wc.x, A20); A21 = fma2(v, wc.y, A21);
            v = splat2(h3.z); A30 = fma2(v, wc.x, A30); A31 = fma2(v, wc.y, A31);
            v = splat2(h0.w); A00 = fma2(v, wd.x, A00); A01 = fma2(v, wd.y, A01);
            v = splat2(h1.w); A10 = fma2(v, wd.x, A10); A11 = fma2(v, wd.y, A11);
            v = splat2(h2.w); A20 = fma2(v, wd.x, A20); A21 = fma2(v, wd.y, A21);
            v = splat2(h3.w); A30 = fma2(v, wd.x, A30); A31 = fma2(v, wd.y, A31);
        }
        {
            float2 p, q;
            p = unpack2(A00); q = unpack2(A01);
            *reinterpret_cast<float4*>(&gsm[(r0 + 0) * GLD + c4]) = make_float4(p.x, p.y, q.x, q.y);
            p = unpack2(A10); q = unpack2(A11);
            *reinterpret_cast<float4*>(&gsm[(r0 + 1) * GLD + c4]) = make_float4(p.x, p.y, q.x, q.y);
            p = unpack2(A20); q = unpack2(A21);
            *reinterpret_cast<float4*>(&gsm[(r0 + 2) * GLD + c4]) = make_float4(p.x, p.y, q.x, q.y);
            p = unpack2(A30); q = unpack2(A31);
            *reinterpret_cast<float4*>(&gsm[(r0 + 3) * GLD + c4]) = make_float4(p.x, p.y, q.x, q.y);
        }
        __syncthreads();

        // ---- cell/hidden update for (row rr, units u0..u0+3) ----
        {
            float4 gi = *reinterpret_cast<const float4*>(&gsm[rr * GLD +  0 + u0]);
            float4 gf = *reinterpret_cast<const float4*>(&gsm[rr * GLD + 16 + u0]);
            float4 gg = *reinterpret_cast<const float4*>(&gsm[rr * GLD + 32 + u0]);
            float4 go = *reinterpret_cast<const float4*>(&gsm[rr * GLD + 48 + u0]);

            c0 = sigf(gf.x) * c0 + sigf(gi.x) * tanh_fast(gg.x);
            c1 = sigf(gf.y) * c1 + sigf(gi.y) * tanh_fast(gg.y);
            c2 = sigf(gf.z) * c2 + sigf(gi.z) * tanh_fast(gg.z);
            c3 = sigf(gf.w) * c3 + sigf(gi.w) * tanh_fast(gg.w);

            float4 hv;
            hv.x = sigf(go.x) * tanh_fast(c0);
            hv.y = sigf(go.y) * tanh_fast(c1);
            hv.z = sigf(go.z) * tanh_fast(c2);
            hv.w = sigf(go.w) * tanh_fast(c3);
            *reinterpret_cast<float4*>(&g_h[s & 1][g][rr][slice * HS + u0]) = hv;
        }
        __syncthreads();   // all h writes issued; gsm/xh reads for step s done

        // ---- sense-reversing group barrier (16 CTAs of this batch group) ----
        if (tid == 0) {
            __threadfence();                         // release h writes
            int prev = atomicAdd(&g_bar_count[g], 1);
            if (prev == NSLICE - 1) {
                atomicExch(&g_bar_count[g], 0);
                __threadfence();                     // reset visible before sense
                atomicExch(&g_bar_sense[g], sense);
            } else {
                volatile int* sp = &g_bar_sense[g];
                while (*sp != sense) __nanosleep(32);
                __threadfence();                     // acquire peers' h writes
            }
        }
        __syncthreads();
        sense ^= 1;
    }

    // ---- final projection (slice 0 of each group): out = h_n @ W_out + b ---
    if (slice == 0) {
        const int wid = tid >> 5, lane = tid & 31;
        const float bo = b_out[0];
        for (int r = wid; r < BT; r += 8) {
            const float* hr = &g_h[(SEQ - 1) & 1][g][r][0];
            float ssum = 0.0f;
            #pragma unroll
            for (int n = lane; n < HIDDEN; n += 32)
                ssum += hr[n] * W_out[n];
            #pragma unroll
            for (int off = 16; off > 0; off >>= 1)
                ssum += __shfl_xor_sync(0xFFFFFFFFu, ssum, off);
            if (lane == 0) out[bb + r] = ssum + bo;
        }
    }
}

// ---------------------------------------------------------------------------
extern "C" void kernel_launch(void* const* d_in, const int* in_sizes, int n_in,
                              void* d_out, int out_size) {
    const float* x     = (const float*)d_in[0];
    const float* W_ih  = (const float*)d_in[1];
    const float* W_hh  = (const float*)d_in[2];
    const float* b_ih  = (const float*)d_in[3];
    const float* b_hh  = (const float*)d_in[4];
    const float* W_out = (const float*)d_in[5];
    const float* b_out = (const float*)d_in[6];
    float* out = (float*)d_out;

    cudaFuncSetAttribute(lstm_kernel,
                         cudaFuncAttributeMaxDynamicSharedMemorySize, SMEM_BYTES);
    lstm_kernel<<<NCTA, NTHR, SMEM_BYTES>>>(x, W_ih, W_hh, b_ih, b_hh,
                                            W_out, b_out, out);
}